// round 17
// baseline (speedup 1.0000x reference)
#include <cuda_runtime.h>
#include <cuda_fp16.h>
#include <cstdint>

#define Bsz 4
#define Hsz 16
#define Ssz 2048
#define Dsz 128
#define BM 128
#define BN 64
#define NT 256
#define NEG_INF -1e30f

// smem byte offsets
#define SM_Q 0            // 32 KB packed A-fragments
#define SM_K0 32768       // 16 KB packed B-fragments (K)
#define SM_K1 49152
#define SM_V0 65536       // 16 KB packed B-fragments (Vt)
#define SM_V1 81920
#define SM_TOTAL 98304

// packed fp16 scratch, fragment-ready layouts (written by prepass each launch)
// Qpk: [bh][mt 0..127][kt 0..7][lane 0..31] x 16B  (A-frag: rows g,g+8 x words c0,c0+4)
// Kpk: [bh][nt 0..255][kt 0..7][lane 0..31] x 8B   (B-frag: words c0,c0+4)
// Vpk: [bh][n64 0..31][kt 0..3][dt 0..15][lane] x 8B
__device__ uint4 QpkG[(size_t)Bsz * Hsz * 128 * 8 * 32];
__device__ uint2 KpkG[(size_t)Bsz * Hsz * 256 * 8 * 32];
__device__ uint2 VpkG[(size_t)Bsz * Hsz * 32 * 4 * 16 * 32];

__device__ __forceinline__ uint32_t smem_u32(const void* p) {
  uint32_t a;
  asm("{ .reg .u64 t; cvta.to.shared.u64 t, %1; cvt.u32.u64 %0, t; }" : "=r"(a) : "l"(p));
  return a;
}
__device__ __forceinline__ void lds128(uint32_t* r, uint32_t a) {
  asm volatile("ld.shared.v4.b32 {%0,%1,%2,%3}, [%4];"
               : "=r"(r[0]), "=r"(r[1]), "=r"(r[2]), "=r"(r[3]) : "r"(a));
}
__device__ __forceinline__ void lds64(uint32_t* r, uint32_t a) {
  asm volatile("ld.shared.v2.b32 {%0,%1}, [%2];" : "=r"(r[0]), "=r"(r[1]) : "r"(a));
}
__device__ __forceinline__ float ex2f(float x) {
  float y;
  asm("ex2.approx.f32 %0, %1;" : "=f"(y) : "f"(x));
  return y;
}
__device__ __forceinline__ uint32_t h2ex2(uint32_t x) {
  uint32_t y;
  asm("ex2.approx.f16x2 %0, %1;" : "=r"(y) : "r"(x));
  return y;
}
#define CP16(dst, src) \
  asm volatile("cp.async.cg.shared.global [%0], [%1], 16;" ::"r"(dst), "l"(src) : "memory")
#define CP_COMMIT() asm volatile("cp.async.commit_group;" ::: "memory")
#define CP_WAIT1() asm volatile("cp.async.wait_group 1;" ::: "memory")
#define CP_WAIT0() asm volatile("cp.async.wait_group 0;" ::: "memory")

__device__ __forceinline__ void mma_f16(float* d, const uint32_t* a, const uint32_t* b) {
  asm volatile(
      "mma.sync.aligned.m16n8k16.row.col.f32.f16.f16.f32 "
      "{%0,%1,%2,%3}, {%4,%5,%6,%7}, {%8,%9}, {%0,%1,%2,%3};"
      : "+f"(d[0]), "+f"(d[1]), "+f"(d[2]), "+f"(d[3])
      : "r"(a[0]), "r"(a[1]), "r"(a[2]), "r"(a[3]), "r"(b[0]), "r"(b[1]));
}

// ------------- prepass: Q -> A-fragment pack (scale includes log2e) -------------
__global__ void prep_qpk(const float* __restrict__ q) {
  const float scl = 0.08838834764831845f * 1.4426950408889634f;  // 1/sqrt(128) * log2e
  const uint32_t u = blockIdx.x * 256 + threadIdx.x;  // (bh, mt, kt, lane)
  const int lane = u & 31, kt = (u >> 5) & 7, mt = (u >> 8) & 127, bh = u >> 15;
  const int g = lane >> 2, t4 = lane & 3;
  const int r0 = mt * 16 + g;
  const int c0 = kt * 8 + t4;
  const float* q0 = q + ((size_t)bh * Ssz + r0) * Dsz;
  const float* q1 = q0 + 8 * Dsz;
  float2 f0 = *(const float2*)(q0 + 2 * c0);
  float2 f1 = *(const float2*)(q1 + 2 * c0);
  float2 f2 = *(const float2*)(q0 + 2 * c0 + 8);
  float2 f3 = *(const float2*)(q1 + 2 * c0 + 8);
  uint4 w;
  __half2 h;
  h = __floats2half2_rn(f0.x * scl, f0.y * scl); w.x = *(uint32_t*)&h;
  h = __floats2half2_rn(f1.x * scl, f1.y * scl); w.y = *(uint32_t*)&h;
  h = __floats2half2_rn(f2.x * scl, f2.y * scl); w.z = *(uint32_t*)&h;
  h = __floats2half2_rn(f3.x * scl, f3.y * scl); w.w = *(uint32_t*)&h;
  QpkG[u] = w;
}

// ------------- prepass: K -> B-fragment pack -------------
__global__ void prep_kpk(const float* __restrict__ k) {
  const uint32_t u = blockIdx.x * 256 + threadIdx.x;  // (bh, nt, kt, g)
  const int g = u & 7, kt = (u >> 3) & 7, nt = (u >> 6) & 255, bh = u >> 14;
  const int n = nt * 8 + g;
  const float* kp = k + ((size_t)bh * Ssz + n) * Dsz + kt * 16;
  float4 f[4];
#pragma unroll
  for (int i = 0; i < 4; i++) f[i] = *(const float4*)(kp + i * 4);
  const float* ff = (const float*)f;  // 16 floats = this (row, kt) chunk
  uint32_t w[8];
#pragma unroll
  for (int t4 = 0; t4 < 4; t4++)
#pragma unroll
    for (int wi = 0; wi < 2; wi++) {
      int d = (t4 + 4 * wi) * 2;
      __half2 h = __floats2half2_rn(ff[d], ff[d + 1]);
      w[t4 * 2 + wi] = *(uint32_t*)&h;
    }
  uint4* dst = (uint4*)&KpkG[(size_t)u * 4];  // (bh,nt,kt,g) -> 4 uint2 = 32B
  dst[0] = make_uint4(w[0], w[1], w[2], w[3]);
  dst[1] = make_uint4(w[4], w[5], w[6], w[7]);
}

// ------------- prepass: V -> transposed B-fragment pack (smem staged) -------------
__global__ void prep_vpk(const float* __restrict__ v) {
  __shared__ float tile[64][33];
  const int n64 = blockIdx.x, dg = blockIdx.y, bh = blockIdx.z;
  const int n0 = n64 * 64, d0 = dg * 32;
  const int tx = threadIdx.x, ty = threadIdx.y;  // 32 x 8
  const float* vp = v + (size_t)bh * Ssz * Dsz;
#pragma unroll
  for (int j = 0; j < 8; j++)
    tile[ty + j * 8][tx] = vp[(size_t)(n0 + ty + j * 8) * Dsz + d0 + tx];
  __syncthreads();
  const uint32_t uu = ty * 32 + tx;
#pragma unroll
  for (int sblk = 0; sblk < 2; sblk++) {
    const uint32_t s = uu + sblk * 256;  // (kt, dtl, lane)
    const int lane = s & 31, dtl = (s >> 5) & 3, kt = s >> 7;
    const int g = lane >> 2, t4 = lane & 3;
    const int ln = 2 * (kt * 8 + t4);
    const int dl = dtl * 8 + g;
    __half2 h0 = __floats2half2_rn(tile[ln][dl], tile[ln + 1][dl]);
    __half2 h1 = __floats2half2_rn(tile[ln + 8][dl], tile[ln + 9][dl]);
    const int dt = dg * 4 + dtl;
    size_t idx = ((((size_t)bh * 32 + n64) * 4 + kt) * 16 + dt) * 32 + lane;
    VpkG[idx] = make_uint2(*(uint32_t*)&h0, *(uint32_t*)&h1);
  }
}

// ---------------- contiguous tile prefetch via cp.async ----------------
__device__ __forceinline__ void kv_fetch(uint32_t smb, const char* Ksrc, const char* Vsrc,
                                         int buf, int tid) {
  const uint32_t kb = smb + (buf ? SM_K1 : SM_K0);
  const uint32_t vb = smb + (buf ? SM_V1 : SM_V0);
#pragma unroll 4
  for (int i = tid; i < 1024; i += NT) CP16(kb + i * 16, Ksrc + i * 16);
#pragma unroll 4
  for (int i = tid; i < 1024; i += NT) CP16(vb + i * 16, Vsrc + i * 16);
}

__global__ __launch_bounds__(NT, 1) void fa_fp16(float* __restrict__ gout) {
  extern __shared__ __align__(16) char sm[];
  const uint32_t smb = smem_u32(sm);

  const int bh = blockIdx.y;
  const int qt = gridDim.x - 1 - blockIdx.x;  // heavy q-tiles first
  const int m0 = qt * BM;
  const char* Qsrc = (const char*)QpkG + (size_t)bh * 524288 + (size_t)qt * 32768;
  const char* Kbh = (const char*)KpkG + (size_t)bh * 524288;
  const char* Vbh = (const char*)VpkG + (size_t)bh * 524288;
  float* out = gout + (size_t)bh * Ssz * Dsz;

  const int tid = threadIdx.x;
  const int warp = tid >> 5;
  const int lane = tid & 31;
  const int g = lane >> 2;
  const int t4 = lane & 3;

  // Q (32 KB) + KV tile 0, one commit group
#pragma unroll 4
  for (int i = tid; i < 2048; i += NT) CP16(smb + SM_Q + i * 16, Qsrc + i * 16);
  kv_fetch(smb, Kbh, Vbh, 0, tid);
  CP_COMMIT();

  // each warp owns one 16-row m-tile (mt = warp); its packed block is 4 KB
  const uint32_t qbase = smb + SM_Q + (uint32_t)warp * 4096 + (uint32_t)lane * 16;
  const uint32_t loff = (uint32_t)lane * 8;

  float o[16][4];
  float mi[2] = {NEG_INF, NEG_INF};
  float li[2] = {0.f, 0.f};
#pragma unroll
  for (int b = 0; b < 16; b++)
#pragma unroll
    for (int c = 0; c < 4; c++) o[b][c] = 0.f;

  const int tmax = 2 * qt + 1;

  for (int t = 0; t <= tmax; t++) {
    const int n0 = t * BN;
    if (t < tmax) {
      kv_fetch(smb, Kbh + (size_t)(t + 1) * 16384, Vbh + (size_t)(t + 1) * 16384,
               (t + 1) & 1, tid);
      CP_COMMIT();
      CP_WAIT1();
    } else {
      CP_WAIT0();
    }
    __syncthreads();

    const uint32_t kb = smb + ((t & 1) ? SM_K1 : SM_K0) + loff;
    const uint32_t vb = smb + ((t & 1) ? SM_V1 : SM_V0) + loff;

    // ---- S = Q @ K^T : 1 m-tile x 8 n-tiles ----
    float sa[8][4];
#pragma unroll
    for (int b = 0; b < 8; b++)
#pragma unroll
      for (int c = 0; c < 4; c++) sa[b][c] = 0.f;

#pragma unroll
    for (int kt = 0; kt < 8; kt++) {
      uint32_t afr[4];
      lds128(afr, qbase + (uint32_t)kt * 512);
#pragma unroll
      for (int nt = 0; nt < 8; nt++) {
        uint32_t bfr[2];
        lds64(bfr, kb + (uint32_t)(nt * 8 + kt) * 256);
        mma_f16(sa[nt], afr, bfr);
      }
    }

    // ---- mask + online softmax (log2 domain, f16x2 exp); P packed in registers ----
    uint32_t ph[8][2];
    const bool needmask = (n0 + BN - 1) > m0;
#pragma unroll
    for (int rr = 0; rr < 2; rr++) {
      const int grow = m0 + warp * 16 + rr * 8 + g;
      if (needmask) {
#pragma unroll
        for (int nt = 0; nt < 8; nt++) {
          int col = n0 + nt * 8 + 2 * t4;
          if (col > grow) sa[nt][rr * 2 + 0] = NEG_INF;
          if (col + 1 > grow) sa[nt][rr * 2 + 1] = NEG_INF;
        }
      }
      float mx = NEG_INF;
#pragma unroll
      for (int nt = 0; nt < 8; nt++) {
        mx = fmaxf(mx, sa[nt][rr * 2 + 0]);
        mx = fmaxf(mx, sa[nt][rr * 2 + 1]);
      }
      mx = fmaxf(mx, __shfl_xor_sync(0xffffffffu, mx, 1));
      mx = fmaxf(mx, __shfl_xor_sync(0xffffffffu, mx, 2));

      const float mnew = fmaxf(mi[rr], mx);
      const float alpha = ex2f(mi[rr] - mnew);
      float rs = 0.f;
#pragma unroll
      for (int nt = 0; nt < 8; nt++) {
        __half2 hs = __floats2half2_rn(sa[nt][rr * 2 + 0] - mnew,
                                       sa[nt][rr * 2 + 1] - mnew);
        uint32_t hp = h2ex2(*(uint32_t*)&hs);
        ph[nt][rr] = hp;
        float2 f = __half22float2(*(__half2*)&hp);
        rs += f.x + f.y;
      }
      rs += __shfl_xor_sync(0xffffffffu, rs, 1);
      rs += __shfl_xor_sync(0xffffffffu, rs, 2);

      li[rr] = li[rr] * alpha + rs;
      mi[rr] = mnew;
      if (alpha != 1.0f) {
#pragma unroll
        for (int dt = 0; dt < 16; dt++) {
          o[dt][rr * 2 + 0] *= alpha;
          o[dt][rr * 2 + 1] *= alpha;
        }
      }
    }

    // ---- O += P @ Vt ----
#pragma unroll
    for (int kt = 0; kt < 4; kt++) {
      uint32_t afr[4];
      afr[0] = ph[2 * kt + 0][0];
      afr[1] = ph[2 * kt + 0][1];
      afr[2] = ph[2 * kt + 1][0];
      afr[3] = ph[2 * kt + 1][1];
#pragma unroll
      for (int dt = 0; dt < 16; dt++) {
        uint32_t bfr[2];
        lds64(bfr, vb + (uint32_t)(kt * 16 + dt) * 256);
        mma_f16(o[dt], afr, bfr);
      }
    }
    __syncthreads();  // all warps done with this tile before buffer overwrite
  }

  // ---- epilogue: normalize, store fp32 ----
#pragma unroll
  for (int rr = 0; rr < 2; rr++) {
    const float inv = 1.0f / li[rr];
    const size_t rowaddr = (size_t)(m0 + warp * 16 + rr * 8 + g) * Dsz;
#pragma unroll
    for (int dt = 0; dt < 16; dt++) {
      float2 ov;
      ov.x = o[dt][rr * 2 + 0] * inv;
      ov.y = o[dt][rr * 2 + 1] * inv;
      *(float2*)&out[rowaddr + dt * 8 + 2 * t4] = ov;
    }
  }
}

extern "C" void kernel_launch(void* const* d_in, const int* in_sizes, int n_in,
                              void* d_out, int out_size) {
  const int qkv_elems = Bsz * Hsz * Ssz * Dsz;
  const float* ptrs[3] = {nullptr, nullptr, nullptr};
  int np = 0;
  for (int i = 0; i < n_in && np < 3; i++) {
    if (in_sizes[i] == qkv_elems) ptrs[np++] = (const float*)d_in[i];
  }

  prep_qpk<<<Bsz * Hsz * 128 * 8 * 32 / 256, 256>>>(ptrs[0]);
  prep_kpk<<<Bsz * Hsz * 256 * 8 * 8 / 256, 256>>>(ptrs[1]);
  prep_vpk<<<dim3(32, 4, Bsz * Hsz), dim3(32, 8)>>>(ptrs[2]);

  cudaFuncSetAttribute(fa_fp16, cudaFuncAttributeMaxDynamicSharedMemorySize, SM_TOTAL);
  dim3 grid(Ssz / BM, Bsz * Hsz);
  fa_fp16<<<grid, NT, SM_TOTAL>>>((float*)d_out);
}